// round 13
// baseline (speedup 1.0000x reference)
#include <cuda_runtime.h>

// Problem constants (fixed shapes from setup_inputs)
#define NB      64
#define T_LEN   2048
#define DDIM    80
#define N_ROWS  (NB * T_LEN)          // 131072
#define N_ELEM  (N_ROWS * DDIM)       // 10,485,760
#define VPR     (DDIM / 4)            // 20 float4 per row

#define GTHREADS 256
#define GBLOCKS  1180                 // ~8 CTAs/SM AND stride % 20 == 0
#define STRIDE   (GBLOCKS * GTHREADS) // 302080 = 20 * 15104
#define ROWSTEP  (STRIDE / VPR)       // 15104 rows per loop step

// Scratch (no device allocation allowed)
__device__ float        g_pc[GBLOCKS];
__device__ float        g_pl[GBLOCKS];
__device__ unsigned int g_count = 0;

__device__ __forceinline__ float lg2f(float x) {
    float y; asm("lg2.approx.f32 %0, %1;" : "=f"(y) : "f"(x)); return y;
}

// exp(-32*|d|) approx, NO conversion instruction, NO xor (R12 -> R13 delta):
// target bits i = B - A*|d|, A = 46.166*2^23, B = (127-0.05639)*2^23.
// Encode i/256 in the float window [2^23, 2^24):
//   f = 2^23 + (B - A*dc)/256 ; bits(f) = 0x4B000000 + round((B - A*dc)/256)
// Recover: bits(f) << 8 == i  exactly, because 0x4B000000 << 8 == 0 (mod 2^32)
// — the window anchor self-annihilates, killing the per-tap LOP3.
// Window rounding = 256 target-bit ULPs = 2^-15 relative: negligible.
// Clamp at 2.74 keeps f inside the window; clamped tail is a ~5e-39 denormal
// where the true value is <= 8.6e-39 — absorbed by the 1e-37 seed.
__device__ __forceinline__ float fexp2n(float d) {    // d = signed raw diff
    float dc = fminf(fabsf(d), 2.74f);                // FMNMX, |.| folded
    float f  = fmaf(dc, -1512775.3957f, 12548296.2f); // FFMA-imm, RN rounds
    return __uint_as_float(__float_as_uint(f) << 8);  // SHF only
}

__global__ void __launch_bounds__(GTHREADS, 7)
jitter_fused(const float* __restrict__ in, const float* __restrict__ tg,
             float* __restrict__ out)
{
    const unsigned t = blockIdx.x * GTHREADS + threadIdx.x;

    // Loop-invariant (STRIDE is a multiple of VPR): computed exactly once.
    const unsigned jj = t % VPR;          // float4 slot within row
    const unsigned r0 = t / VPR;          // starting row
    const int  base = jj * 4;
    const bool lv   = (jj > 0);
    const bool rv   = (jj < VPR - 1);

    float accC = 0.0f;   // sum of center abs-diffs
    float accL = 0.0f;   // sum of lg2(softmin-sum)

    #pragma unroll 1
    for (unsigned row = r0; row < N_ROWS; row += ROWSTEP) {
        const unsigned i = row & (T_LEN - 1);

        const float* ip = in + (size_t)row * DDIM + base;
        const float* tp = tg + (size_t)row * DDIM + base;

        float4 x4 = *reinterpret_cast<const float4*>(ip);
        float x[4] = {x4.x, x4.y, x4.z, x4.w};

        // 3 target rows (i-1, i, i+1) x 6 cols (j-1 .. j+4), zero-padded OOB
        float tv[3][6];
        const float* rows[3] = {tp - DDIM, tp, tp + DDIM};
        const bool   rok[3]  = {i > 0, true, i < T_LEN - 1};

        #pragma unroll
        for (int r = 0; r < 3; r++) {
            if (rok[r]) {
                float4 t4 = *reinterpret_cast<const float4*>(rows[r]);
                tv[r][1] = t4.x; tv[r][2] = t4.y; tv[r][3] = t4.z; tv[r][4] = t4.w;
                tv[r][0] = lv ? rows[r][-1] : 0.0f;
                tv[r][5] = rv ? rows[r][4]  : 0.0f;
            } else {
                #pragma unroll
                for (int c = 0; c < 6; c++) tv[r][c] = 0.0f;
            }
        }

        #pragma unroll
        for (int e = 0; e < 4; e++) {
            float xv = x[e];
            float dcen = xv - tv[1][e + 1];           // center diff (signed)
            float s0 = 1e-37f + fexp2n(dcen);         // underflow-guard seed
            float s1 = fexp2n(xv - tv[0][e + 0]);
            float s2 = fexp2n(xv - tv[0][e + 1]);
            float s3 = fexp2n(xv - tv[0][e + 2]);
            s0 += fexp2n(xv - tv[1][e + 0]);
            s1 += fexp2n(xv - tv[1][e + 2]);
            s2 += fexp2n(xv - tv[2][e + 0]);
            s3 += fexp2n(xv - tv[2][e + 1]);
            s0 += fexp2n(xv - tv[2][e + 2]);
            float s = (s0 + s1) + (s2 + s3);
            accC += fabsf(dcen);                      // exact center term
            accL += lg2f(s);
        }
    }

    // ---- deterministic block tree reduction ----
    __shared__ float shc[GTHREADS];
    __shared__ float shl[GTHREADS];
    shc[threadIdx.x] = accC;
    shl[threadIdx.x] = accL;
    __syncthreads();
    #pragma unroll
    for (int off = GTHREADS / 2; off > 0; off >>= 1) {
        if (threadIdx.x < off) {
            shc[threadIdx.x] += shc[threadIdx.x + off];
            shl[threadIdx.x] += shl[threadIdx.x + off];
        }
        __syncthreads();
    }

    // ---- fused final reduction via ticket (last block) ----
    __shared__ bool isLast;
    if (threadIdx.x == 0) {
        g_pc[blockIdx.x] = shc[0];
        g_pl[blockIdx.x] = shl[0];
        __threadfence();
        unsigned ticket = atomicAdd(&g_count, 1u);
        isLast = (ticket == GBLOCKS - 1);
    }
    __syncthreads();

    if (isLast) {
        __shared__ double dsc[GTHREADS];
        __shared__ double dsl[GTHREADS];
        double dc = 0.0, dl = 0.0;
        for (int k = threadIdx.x; k < GBLOCKS; k += GTHREADS) {
            dc += (double)__ldcg(&g_pc[k]);
            dl += (double)__ldcg(&g_pl[k]);
        }
        dsc[threadIdx.x] = dc;
        dsl[threadIdx.x] = dl;
        __syncthreads();
        #pragma unroll
        for (int off = GTHREADS / 2; off > 0; off >>= 1) {
            if (threadIdx.x < off) {
                dsc[threadIdx.x] += dsc[threadIdx.x + off];
                dsl[threadIdx.x] += dsl[threadIdx.x + off];
            }
            __syncthreads();
        }
        if (threadIdx.x == 0) {
            const double C2d = -0.021660849392498291;  // -ln(2)/32
            double res = (0.5 / (double)N_ELEM) * (dsc[0] + C2d * dsl[0]);
            out[0] = (float)res;
            g_count = 0;   // reset ticket for graph replay
        }
    }
}

extern "C" void kernel_launch(void* const* d_in, const int* in_sizes, int n_in,
                              void* d_out, int out_size)
{
    const float* in = (const float*)d_in[0];
    const float* tg = (const float*)d_in[1];
    float* out = (float*)d_out;

    jitter_fused<<<GBLOCKS, GTHREADS>>>(in, tg, out);
}

// round 14
// speedup vs baseline: 1.0267x; 1.0267x over previous
#include <cuda_runtime.h>

// Problem constants (fixed shapes from setup_inputs)
#define NB      64
#define T_LEN   2048
#define DDIM    80
#define N_ROWS  (NB * T_LEN)          // 131072
#define N_ELEM  (N_ROWS * DDIM)       // 10,485,760
#define VPR     (DDIM / 4)            // 20 float4 per row

#define GTHREADS 256
#define GBLOCKS  1180                 // stride % 20 == 0
#define STRIDE   (GBLOCKS * GTHREADS) // 302080 = 20 * 15104
#define ROWSTEP  (STRIDE / VPR)       // 15104 rows per loop step

// Scratch (no device allocation allowed)
__device__ float        g_pc[GBLOCKS];
__device__ float        g_pl[GBLOCKS];
__device__ unsigned int g_count = 0;

__device__ __forceinline__ float lg2f(float x) {
    float y; asm("lg2.approx.f32 %0, %1;" : "=f"(y) : "f"(x)); return y;
}

// exp(-32*|d|) approx, no conversion instruction (proven R12/R13 form):
// target bits i = B - A*|d|; encode i/256 in the float window [2^23, 2^24):
//   f = fma(|d|_clamped, -A/256, 2^23 + B/256); bits(f) << 8 == i exactly
// because the window anchor 0x4B000000 << 8 == 0 (mod 2^32).
__device__ __forceinline__ float fexp2n(float d) {    // generic tap, clamp 2.74
    float dc = fminf(fabsf(d), 2.74f);                // FMNMX, |.| folded
    float f  = fmaf(dc, -1512775.3957f, 12548296.2f); // FFMA-imm, RN rounds
    return __uint_as_float(__float_as_uint(f) << 8);  // SHF only
}
// Center tap: clamp at 2.0 so the result is >= ~1e-28 (a NORMAL float),
// making the softmin sum s >= 1e-28 unconditionally -> the old 1e-37 seed
// FADD is deleted. Bias only when ALL nine diffs exceed 2 (~3e-4 of elems).
__device__ __forceinline__ float fexp2c(float d) {
    float dc = fminf(fabsf(d), 2.0f);
    float f  = fmaf(dc, -1512775.3957f, 12548296.2f);
    return __uint_as_float(__float_as_uint(f) << 8);
}

__global__ void __launch_bounds__(GTHREADS)
jitter_fused(const float* __restrict__ in, const float* __restrict__ tg,
             float* __restrict__ out)
{
    const unsigned t = blockIdx.x * GTHREADS + threadIdx.x;

    // Loop-invariant (STRIDE is a multiple of VPR): computed exactly once.
    const unsigned jj = t % VPR;          // float4 slot within row
    const unsigned r0 = t / VPR;          // starting row
    const int  base = jj * 4;
    const bool lv   = (jj > 0);
    const bool rv   = (jj < VPR - 1);

    float accC = 0.0f;   // sum of center abs-diffs
    float accL = 0.0f;   // sum of lg2(softmin-sum)

    // unroll 2: ptxas batches two iterations' loads ahead of the math,
    // doubling MLP and hiding L2/DRAM latency behind independent FMA work.
    #pragma unroll 2
    for (unsigned row = r0; row < N_ROWS; row += ROWSTEP) {
        const unsigned i = row & (T_LEN - 1);

        const float* ip = in + (size_t)row * DDIM + base;
        const float* tp = tg + (size_t)row * DDIM + base;

        float4 x4 = *reinterpret_cast<const float4*>(ip);
        float x[4] = {x4.x, x4.y, x4.z, x4.w};

        // 3 target rows (i-1, i, i+1) x 6 cols (j-1 .. j+4), zero-padded OOB
        float tv[3][6];
        const float* rows[3] = {tp - DDIM, tp, tp + DDIM};
        const bool   rok[3]  = {i > 0, true, i < T_LEN - 1};

        #pragma unroll
        for (int r = 0; r < 3; r++) {
            if (rok[r]) {
                float4 t4 = *reinterpret_cast<const float4*>(rows[r]);
                tv[r][1] = t4.x; tv[r][2] = t4.y; tv[r][3] = t4.z; tv[r][4] = t4.w;
                tv[r][0] = lv ? rows[r][-1] : 0.0f;
                tv[r][5] = rv ? rows[r][4]  : 0.0f;
            } else {
                #pragma unroll
                for (int c = 0; c < 6; c++) tv[r][c] = 0.0f;
            }
        }

        #pragma unroll
        for (int e = 0; e < 4; e++) {
            float xv = x[e];
            float dcen = xv - tv[1][e + 1];           // center diff (signed)
            float s0 = fexp2c(dcen);                  // normal-float floor
            float s1 = fexp2n(xv - tv[0][e + 0]);
            float s2 = fexp2n(xv - tv[0][e + 1]);
            float s3 = fexp2n(xv - tv[0][e + 2]);
            s0 += fexp2n(xv - tv[1][e + 0]);
            s1 += fexp2n(xv - tv[1][e + 2]);
            s2 += fexp2n(xv - tv[2][e + 0]);
            s3 += fexp2n(xv - tv[2][e + 1]);
            s0 += fexp2n(xv - tv[2][e + 2]);
            float s = (s0 + s1) + (s2 + s3);
            accC += fabsf(dcen);                      // exact center term
            accL += lg2f(s);
        }
    }

    // ---- deterministic block tree reduction ----
    __shared__ float shc[GTHREADS];
    __shared__ float shl[GTHREADS];
    shc[threadIdx.x] = accC;
    shl[threadIdx.x] = accL;
    __syncthreads();
    #pragma unroll
    for (int off = GTHREADS / 2; off > 0; off >>= 1) {
        if (threadIdx.x < off) {
            shc[threadIdx.x] += shc[threadIdx.x + off];
            shl[threadIdx.x] += shl[threadIdx.x + off];
        }
        __syncthreads();
    }

    // ---- fused final reduction via ticket (last block) ----
    __shared__ bool isLast;
    if (threadIdx.x == 0) {
        g_pc[blockIdx.x] = shc[0];
        g_pl[blockIdx.x] = shl[0];
        __threadfence();
        unsigned ticket = atomicAdd(&g_count, 1u);
        isLast = (ticket == GBLOCKS - 1);
    }
    __syncthreads();

    if (isLast) {
        __shared__ double dsc[GTHREADS];
        __shared__ double dsl[GTHREADS];
        double dc = 0.0, dl = 0.0;
        for (int k = threadIdx.x; k < GBLOCKS; k += GTHREADS) {
            dc += (double)__ldcg(&g_pc[k]);
            dl += (double)__ldcg(&g_pl[k]);
        }
        dsc[threadIdx.x] = dc;
        dsl[threadIdx.x] = dl;
        __syncthreads();
        #pragma unroll
        for (int off = GTHREADS / 2; off > 0; off >>= 1) {
            if (threadIdx.x < off) {
                dsc[threadIdx.x] += dsc[threadIdx.x + off];
                dsl[threadIdx.x] += dsl[threadIdx.x + off];
            }
            __syncthreads();
        }
        if (threadIdx.x == 0) {
            const double C2d = -0.021660849392498291;  // -ln(2)/32
            double res = (0.5 / (double)N_ELEM) * (dsc[0] + C2d * dsl[0]);
            out[0] = (float)res;
            g_count = 0;   // reset ticket for graph replay
        }
    }
}

extern "C" void kernel_launch(void* const* d_in, const int* in_sizes, int n_in,
                              void* d_out, int out_size)
{
    const float* in = (const float*)d_in[0];
    const float* tg = (const float*)d_in[1];
    float* out = (float*)d_out;

    jitter_fused<<<GBLOCKS, GTHREADS>>>(in, tg, out);
}